// round 5
// baseline (speedup 1.0000x reference)
#include <cuda_runtime.h>
#include <math.h>

// Problem constants
#define PP 20
#define NN 1024
#define DD 512
#define TPB 128          // thread t owns d-values [4t, 4t+3]
#define NWARP (TPB / 32)
#define NS 8             // atomic slot count (contention reduction)
#define EPS 1e-8f

// Persistent accumulators. Zero at module load; the LAST block re-zeroes them
// after consuming, so every graph replay starts from zeros deterministically.
__device__ float gS[NS][DD];      // slot-partial of S[d] = sum_n an[n][d]
__device__ float gT[NS][DD];      // slot-partial of T[d] = sum_{p,n} zn[p][n][d]
__device__ float gDiag[NS];       // slot-partial of sum_n (sum_p zn_p) . an
__device__ unsigned int gTicket;  // completed-block counter (reset by last block)

// Fully fused: one block per column n.
// Phase 1: stream 20 rows (float4/thread) from DRAM, cache tile in SMEM,
//          accumulate avg and 20 norm partials; block-reduce 21 sums.
// Phase 2: re-read tile from SMEM, zn = sum_p z_p/||z_p||; diag_n = zn . an.
// Accumulate into slotted global atomics; last block computes the scalar,
// writes out, and re-zeroes all persistent state.
__global__ __launch_bounds__(TPB) void fused_kernel(const float* __restrict__ z,
                                                    float* __restrict__ out) {
    const int n    = blockIdx.x;
    const int t    = threadIdx.x;
    const int wid  = t >> 5;
    const int lane = t & 31;
    const int slot = n & (NS - 1);
    const int d0   = t * 4;

    __shared__ float4 tile[PP][TPB];       // 40 KB: this column's 20 rows
    __shared__ float  wp[NWARP][21];
    __shared__ float  inv[21];             // [p]=1/max(||z_p||,eps), [20]=avg
    __shared__ float  wdg[NWARP];
    __shared__ unsigned int ticket_s;

    const size_t stride = (size_t)NN * DD / 4;   // float4 stride between patches
    const float4* base =
        reinterpret_cast<const float4*>(z) + (size_t)n * (DD / 4) + t;

    // ---- phase 1: DRAM stream -> smem cache + avg + norm partials ----
    float4 avg = make_float4(0.f, 0.f, 0.f, 0.f);
    float s[21];
    #pragma unroll
    for (int p = 0; p < PP; ++p) {
        float4 v = base[(size_t)p * stride];
        tile[p][t] = v;
        avg.x += v.x; avg.y += v.y; avg.z += v.z; avg.w += v.w;
        s[p] = v.x * v.x + v.y * v.y + v.z * v.z + v.w * v.w;
    }
    const float invP = 1.0f / (float)PP;
    avg.x *= invP; avg.y *= invP; avg.z *= invP; avg.w *= invP;
    s[20] = avg.x * avg.x + avg.y * avg.y + avg.z * avg.z + avg.w * avg.w;

    // ---- block-reduce the 21 sums ----
    #pragma unroll
    for (int i = 0; i < 21; ++i) {
        float v = s[i];
        #pragma unroll
        for (int o = 16; o > 0; o >>= 1)
            v += __shfl_xor_sync(0xffffffffu, v, o);
        s[i] = v;
    }
    if (lane == 0) {
        #pragma unroll
        for (int i = 0; i < 21; ++i) wp[wid][i] = s[i];
    }
    __syncthreads();
    if (t < 21) {
        float v = 0.f;
        #pragma unroll
        for (int w = 0; w < NWARP; ++w) v += wp[w][t];
        inv[t] = 1.0f / fmaxf(sqrtf(v), EPS);
    }
    __syncthreads();

    // ---- phase 2: smem re-read -> zn ----
    float4 zn = make_float4(0.f, 0.f, 0.f, 0.f);
    #pragma unroll
    for (int p = 0; p < PP; ++p) {
        float4 v = tile[p][t];
        const float ip = inv[p];
        zn.x += v.x * ip; zn.y += v.y * ip;
        zn.z += v.z * ip; zn.w += v.w * ip;
    }

    const float inv_avg = inv[20];
    const float an0 = avg.x * inv_avg, an1 = avg.y * inv_avg;
    const float an2 = avg.z * inv_avg, an3 = avg.w * inv_avg;

    // diag_n partial: zn . an
    float dsum = zn.x * an0 + zn.y * an1 + zn.z * an2 + zn.w * an3;
    #pragma unroll
    for (int o = 16; o > 0; o >>= 1)
        dsum += __shfl_xor_sync(0xffffffffu, dsum, o);
    if (lane == 0) wdg[wid] = dsum;

    // slotted global accumulation (128 updates per address)
    atomicAdd(&gS[slot][d0 + 0], an0);
    atomicAdd(&gS[slot][d0 + 1], an1);
    atomicAdd(&gS[slot][d0 + 2], an2);
    atomicAdd(&gS[slot][d0 + 3], an3);
    atomicAdd(&gT[slot][d0 + 0], zn.x);
    atomicAdd(&gT[slot][d0 + 1], zn.y);
    atomicAdd(&gT[slot][d0 + 2], zn.z);
    atomicAdd(&gT[slot][d0 + 3], zn.w);

    __syncthreads();
    if (t == 0) {
        float dg = 0.f;
        #pragma unroll
        for (int w = 0; w < NWARP; ++w) dg += wdg[w];
        atomicAdd(&gDiag[slot], dg);
    }

    // ---- completion ticket (threadFenceReduction pattern) ----
    __threadfence();
    __syncthreads();
    if (t == 0) ticket_s = atomicAdd(&gTicket, 1u);
    __syncthreads();
    if (ticket_s != NN - 1) return;

    // ======== LAST BLOCK: final scalar + state reset ========
    // Each thread owns d-values [4t, 4t+3]; sum slots, dot S.T.
    float v = 0.f;
    #pragma unroll
    for (int j = 0; j < 4; ++j) {
        const int d = d0 + j;
        float S = 0.f, T = 0.f;
        #pragma unroll
        for (int sl = 0; sl < NS; ++sl) { S += gS[sl][d]; T += gT[sl][d]; }
        v += S * T;
    }
    #pragma unroll
    for (int o = 16; o > 0; o >>= 1)
        v += __shfl_xor_sync(0xffffffffu, v, o);
    if (lane == 0) wdg[wid] = v;          // reuse wdg for T.S partials

    float dg_all = 0.f;
    if (t == 0) {
        #pragma unroll
        for (int sl = 0; sl < NS; ++sl) dg_all += gDiag[sl];
    }
    __syncthreads();

    if (t == 0) {
        float ts = 0.f;
        #pragma unroll
        for (int w = 0; w < NWARP; ++w) ts += wdg[w];
        const double count = 20.0 * 1024.0 * 1023.0;
        out[0] = (float)(((double)ts - (double)dg_all) / count - 1.0);
    }

    // re-zero persistent state for the next graph replay
    #pragma unroll
    for (int sl = 0; sl < NS; ++sl) {
        #pragma unroll
        for (int j = 0; j < 4; ++j) {
            gS[sl][d0 + j] = 0.f;
            gT[sl][d0 + j] = 0.f;
        }
    }
    if (t < NS) gDiag[t] = 0.f;
    if (t == 0) gTicket = 0u;
}

extern "C" void kernel_launch(void* const* d_in, const int* in_sizes, int n_in,
                              void* d_out, int out_size) {
    const float* z_list = (const float*)d_in[0];
    // d_in[1] (z_avg) ignored — reference recomputes it from z_list.
    (void)in_sizes; (void)n_in; (void)out_size;
    float* out = (float*)d_out;

    fused_kernel<<<NN, TPB>>>(z_list, out);
}

// round 8
// speedup vs baseline: 1.0964x; 1.0964x over previous
#include <cuda_runtime.h>
#include <math.h>

// Problem constants
#define PP 20
#define NN 1024
#define DD 512
#define TPB 128          // thread t owns d-values [4t, 4t+3]
#define NWARP (TPB / 32)
#define NS 8             // atomic slot count (contention reduction)
#define EPS 1e-8f

// Persistent accumulators. Zero at module load; the LAST block re-zeroes them
// after consuming, so every graph replay starts from zeros deterministically.
__device__ float gS[NS][DD];      // slot-partial of S[d] = sum_n an[n][d]
__device__ float gT[NS][DD];      // slot-partial of T[d] = sum_{p,n} zn[p][n][d]
__device__ float gDiag[NS];       // slot-partial of sum_n (sum_p zn_p) . an
__device__ unsigned int gTicket;  // completed-block counter (reset by last block)

// One block per column n. NO smem tile (kills occupancy): phase 2 re-reads
// global memory, which is L2-resident (whole input 40MB < 126MB L2).
// Phase 1: stream 20 rows (float4/thread), avg + 20 norm partials,
//          block-reduce 21 sums -> 1/max(norm,eps).
// Phase 2: reload rows from L2, zn = sum_p z_p/||z_p||; diag_n = zn . an.
// Slotted global atomics; ticketed last block computes the scalar and resets.
__global__ __launch_bounds__(TPB) void fused_kernel(const float* __restrict__ z,
                                                    float* __restrict__ out) {
    const int n    = blockIdx.x;
    const int t    = threadIdx.x;
    const int wid  = t >> 5;
    const int lane = t & 31;
    const int slot = n & (NS - 1);
    const int d0   = t * 4;

    __shared__ float wp[NWARP][21];
    __shared__ float inv[21];      // [p]=1/max(||z_p||,eps), [20]=avg
    __shared__ float wdg[NWARP];
    __shared__ unsigned int ticket_s;

    const size_t stride = (size_t)NN * DD / 4;   // float4 stride between patches
    const float4* base =
        reinterpret_cast<const float4*>(z) + (size_t)n * (DD / 4) + t;

    // ---- phase 1: avg + norm partials (20 independent LDG.128 in flight) ----
    float4 avg = make_float4(0.f, 0.f, 0.f, 0.f);
    float s[21];
    #pragma unroll
    for (int p = 0; p < PP; ++p) {
        float4 v = base[(size_t)p * stride];
        avg.x += v.x; avg.y += v.y; avg.z += v.z; avg.w += v.w;
        s[p] = v.x * v.x + v.y * v.y + v.z * v.z + v.w * v.w;
    }
    const float invP = 1.0f / (float)PP;
    avg.x *= invP; avg.y *= invP; avg.z *= invP; avg.w *= invP;
    s[20] = avg.x * avg.x + avg.y * avg.y + avg.z * avg.z + avg.w * avg.w;

    // ---- block-reduce the 21 sums ----
    #pragma unroll
    for (int i = 0; i < 21; ++i) {
        float v = s[i];
        #pragma unroll
        for (int o = 16; o > 0; o >>= 1)
            v += __shfl_xor_sync(0xffffffffu, v, o);
        s[i] = v;
    }
    if (lane == 0) {
        #pragma unroll
        for (int i = 0; i < 21; ++i) wp[wid][i] = s[i];
    }
    __syncthreads();
    if (t < 21) {
        float v = 0.f;
        #pragma unroll
        for (int w = 0; w < NWARP; ++w) v += wp[w][t];
        inv[t] = 1.0f / fmaxf(sqrtf(v), EPS);
    }
    __syncthreads();

    // ---- phase 2: reload rows (L2 hit) -> zn ----
    float4 zn = make_float4(0.f, 0.f, 0.f, 0.f);
    #pragma unroll
    for (int p = 0; p < PP; ++p) {
        float4 v = base[(size_t)p * stride];
        const float ip = inv[p];
        zn.x += v.x * ip; zn.y += v.y * ip;
        zn.z += v.z * ip; zn.w += v.w * ip;
    }

    const float inv_avg = inv[20];
    const float an0 = avg.x * inv_avg, an1 = avg.y * inv_avg;
    const float an2 = avg.z * inv_avg, an3 = avg.w * inv_avg;

    // diag_n partial: zn . an
    float dsum = zn.x * an0 + zn.y * an1 + zn.z * an2 + zn.w * an3;
    #pragma unroll
    for (int o = 16; o > 0; o >>= 1)
        dsum += __shfl_xor_sync(0xffffffffu, dsum, o);
    if (lane == 0) wdg[wid] = dsum;

    // slotted global accumulation (128 updates per address)
    atomicAdd(&gS[slot][d0 + 0], an0);
    atomicAdd(&gS[slot][d0 + 1], an1);
    atomicAdd(&gS[slot][d0 + 2], an2);
    atomicAdd(&gS[slot][d0 + 3], an3);
    atomicAdd(&gT[slot][d0 + 0], zn.x);
    atomicAdd(&gT[slot][d0 + 1], zn.y);
    atomicAdd(&gT[slot][d0 + 2], zn.z);
    atomicAdd(&gT[slot][d0 + 3], zn.w);

    __syncthreads();
    if (t == 0) {
        float dg = 0.f;
        #pragma unroll
        for (int w = 0; w < NWARP; ++w) dg += wdg[w];
        atomicAdd(&gDiag[slot], dg);
    }

    // ---- completion ticket (threadFenceReduction pattern) ----
    __threadfence();
    __syncthreads();
    if (t == 0) ticket_s = atomicAdd(&gTicket, 1u);
    __syncthreads();
    if (ticket_s != NN - 1) return;

    // ======== LAST BLOCK: final scalar + state reset ========
    float v = 0.f;
    #pragma unroll
    for (int j = 0; j < 4; ++j) {
        const int d = d0 + j;
        float S = 0.f, T = 0.f;
        #pragma unroll
        for (int sl = 0; sl < NS; ++sl) { S += gS[sl][d]; T += gT[sl][d]; }
        v += S * T;
    }
    #pragma unroll
    for (int o = 16; o > 0; o >>= 1)
        v += __shfl_xor_sync(0xffffffffu, v, o);
    if (lane == 0) wdg[wid] = v;          // reuse wdg for T.S partials

    float dg_all = 0.f;
    if (t == 0) {
        #pragma unroll
        for (int sl = 0; sl < NS; ++sl) dg_all += gDiag[sl];
    }
    __syncthreads();

    if (t == 0) {
        float ts = 0.f;
        #pragma unroll
        for (int w = 0; w < NWARP; ++w) ts += wdg[w];
        const double count = 20.0 * 1024.0 * 1023.0;
        out[0] = (float)(((double)ts - (double)dg_all) / count - 1.0);
    }

    // re-zero persistent state for the next graph replay
    #pragma unroll
    for (int sl = 0; sl < NS; ++sl) {
        #pragma unroll
        for (int j = 0; j < 4; ++j) {
            gS[sl][d0 + j] = 0.f;
            gT[sl][d0 + j] = 0.f;
        }
    }
    if (t < NS) gDiag[t] = 0.f;
    if (t == 0) gTicket = 0u;
}

extern "C" void kernel_launch(void* const* d_in, const int* in_sizes, int n_in,
                              void* d_out, int out_size) {
    const float* z_list = (const float*)d_in[0];
    // d_in[1] (z_avg) ignored — reference recomputes it from z_list.
    (void)in_sizes; (void)n_in; (void)out_size;
    float* out = (float*)d_out;

    fused_kernel<<<NN, TPB>>>(z_list, out);
}